// round 4
// baseline (speedup 1.0000x reference)
#include <cuda_runtime.h>
#include <cuda_bf16.h>
#include <cstdint>

// ---------------- problem constants ----------------
#define IN_CH   256
#define BATCH   8
#define KF      2304            // 9*256
#define NOUT    512
#define L2D     1024
#define MROWS   (BATCH * L2D)   // 8192

// GEMM tiling
#define BK   32                 // k per chunk (4 mma k-atoms of 8)
#define NS   3                  // cp.async pipeline stages
#define NCH  (KF / BK)          // 72
#define TSZ  (128 * BK * 4)     // 16KB per operand tile
#define STAGE (2 * TSZ)         // 32KB
#define SMEM_TOTAL (NS * STAGE) // 96KB

// scratch (__device__ globals: allocation-free rule)
// g_U holds the im2col buffer [b][f][l] flat == A (8192 x 2304) rows,
// with each k-atom of 8 stored in PERMUTED order perm(c) = (c&3)*2 + (c>>2)
// so mma fragment pairs (t, t+4) are adjacent 8B for LDS.64.
__device__ float g_U[(size_t)MROWS * KF];
__device__ float g_BeffT[(size_t)NOUT * KF];   // B^T [co][k], same permutation

// ---------------- helpers ----------------
__device__ __forceinline__ float to_tf32(float v) {
    float r; asm("cvt.rna.tf32.f32 %0, %1;" : "=f"(r) : "f"(v)); return r;
}
__device__ __forceinline__ int kperm(int c) { return ((c & 3) << 1) + (c >> 2); }

__device__ __forceinline__ void cpa16(uint32_t dst, const void* src) {
    asm volatile("cp.async.cg.shared.global [%0], [%1], 16;" :: "r"(dst), "l"(src));
}
#define CP_COMMIT() asm volatile("cp.async.commit_group;" ::: "memory")
#define CP_WAIT1()  asm volatile("cp.async.wait_group 1;" ::: "memory")

// LDS.64 of fragment pair: row, k-atom, t. chunk = atom*2 + (t>>1), XOR row%8.
__device__ __forceinline__ void lds64(const char* base, int row, int atom, int t,
                                      uint32_t& lo, uint32_t& hi) {
    const char* p = base + row * 128 +
                    ((((atom << 1) + (t >> 1)) ^ (row & 7)) << 4) + ((t & 1) << 3);
    asm volatile("ld.shared.v2.b32 {%0, %1}, [%2];"
                 : "=r"(lo), "=r"(hi) : "l"(p));
}
__device__ __forceinline__ void mma8(float* c, const uint32_t* a, const uint32_t* b) {
    asm volatile(
        "mma.sync.aligned.m16n8k8.row.col.f32.tf32.tf32.f32 "
        "{%0,%1,%2,%3}, {%4,%5,%6,%7}, {%8,%9}, {%0,%1,%2,%3};"
        : "+f"(c[0]), "+f"(c[1]), "+f"(c[2]), "+f"(c[3])
        : "r"(a[0]), "r"(a[1]), "r"(a[2]), "r"(a[3]), "r"(b[0]), "r"(b[1]));
}

// ---------------------------------------------------------------------------
// Kernel 1: im2col -> g_U[b][f][l] flat, tf32-rounded, k-atom permuted.
// A-row flat index i = (b*KF+f)*1024 + l; i%8 == l%8, so permute on l%8.
// ---------------------------------------------------------------------------
__global__ void im2col_kernel(const float* __restrict__ x) {
    const int dd = blockIdx.x, ci = blockIdx.y, b = blockIdx.z;
    const int oy = dd / 3 - 1, ox = dd % 3 - 1;      // uniform per block
    const float* xp = x + (((size_t)(b * IN_CH + ci)) << 10);
    float* up = g_U + (((size_t)(b * KF + ci * 9 + dd)) << 10);
    #pragma unroll
    for (int s = 0; s < 4; s++) {
        int l = threadIdx.x + s * 256;
        int h = l >> 5, w = l & 31;
        int y = h + oy, xw = w + ox;
        float v = 0.0f;
        if ((unsigned)y < 32u && (unsigned)xw < 32u) v = xp[(y << 5) + xw];
        up[(l & ~7) + kperm(l & 7)] = to_tf32(v);
    }
}

// ---------------------------------------------------------------------------
// Kernel 2: B^T expansion, tf32-rounded, permuted. BeffT[co][k]=w[p][q][(j-m)&63]
// ---------------------------------------------------------------------------
__global__ void beffT_kernel(const float* __restrict__ wgt) {
    const int co = blockIdx.y;
    const int k = blockIdx.x * 256 + threadIdx.x;
    const int q = k >> 6, m = k & 63;
    const int p = co >> 6, j = co & 63;
    g_BeffT[(size_t)co * KF + (k & ~7) + kperm(k & 7)] =
        to_tf32(wgt[((p * 36 + q) << 6) + ((j - m) & 63)]);
}

// ---------------------------------------------------------------------------
// Kernel 3: tf32 mma.sync GEMM C[8192,512] = A @ B, fused transpose store.
// CTA 128x128, 8 warps (2m x 4n), warp tile 64x32, 3-stage cp.async, LDS.64 frags.
// ---------------------------------------------------------------------------
__global__ void __launch_bounds__(256, 2) gemm_kernel(float* __restrict__ out) {
    extern __shared__ char sm[];
    const int tid = threadIdx.x;
    const int lane = tid & 31;
    const int wid = tid >> 5;
    const int g = lane >> 2, t = lane & 3;
    const int wm = wid >> 2, wn = wid & 3;
    const int bm = blockIdx.y * 128;
    const int bn = blockIdx.x * 128;

    float acc[4][4][4];
    #pragma unroll
    for (int i = 0; i < 4; i++)
        #pragma unroll
        for (int j = 0; j < 4; j++)
            #pragma unroll
            for (int q = 0; q < 4; q++) acc[i][j][q] = 0.0f;

    auto load_chunk = [&](int c, int s) {
        char* As = sm + s * STAGE;
        char* Bs = As + TSZ;
        const int k0 = c * BK;
        #pragma unroll
        for (int i = 0; i < 4; i++) {
            int id = tid + i * 256;
            int row = id >> 3, cj = id & 7;
            uint32_t swo = (uint32_t)(row * 128 + ((cj ^ (row & 7)) << 4));
            cpa16((uint32_t)__cvta_generic_to_shared(As + swo),
                  &g_U[(size_t)(bm + row) * KF + k0 + cj * 4]);
            cpa16((uint32_t)__cvta_generic_to_shared(Bs + swo),
                  &g_BeffT[(size_t)(bn + row) * KF + k0 + cj * 4]);
        }
    };

    auto compute = [&](int s) {
        const char* As = sm + s * STAGE;
        const char* Bs = As + TSZ;
        #pragma unroll
        for (int ka = 0; ka < 4; ka++) {
            uint32_t a[4][4], b[4][2];
            #pragma unroll
            for (int ma = 0; ma < 4; ma++) {
                int r0 = wm * 64 + ma * 16 + g;
                lds64(As, r0,     ka, t, a[ma][0], a[ma][2]);   // (t), (t+4)
                lds64(As, r0 + 8, ka, t, a[ma][1], a[ma][3]);
            }
            #pragma unroll
            for (int na = 0; na < 4; na++)
                lds64(Bs, wn * 32 + na * 8 + g, ka, t, b[na][0], b[na][1]);
            #pragma unroll
            for (int ma = 0; ma < 4; ma++)
                #pragma unroll
                for (int na = 0; na < 4; na++)
                    mma8(acc[ma][na], a[ma], b[na]);
        }
    };

    // prologue: prefetch NS-1 chunks
    #pragma unroll
    for (int s = 0; s < NS - 1; s++) { load_chunk(s, s); CP_COMMIT(); }

    for (int c = 0; c < NCH; c++) {
        CP_WAIT1();
        __syncthreads();
        const int cn = c + NS - 1;
        if (cn < NCH) { load_chunk(cn, cn % NS); CP_COMMIT(); }
        compute(c % NS);
    }

    // epilogue: C[r][co] -> out[b][co][l2], r = b*1024 + l2
    #pragma unroll
    for (int ma = 0; ma < 4; ma++) {
        #pragma unroll
        for (int half = 0; half < 2; half++) {
            const int r = bm + wm * 64 + ma * 16 + g + half * 8;
            const int b = r >> 10;
            const int l2 = r & (L2D - 1);
            float* op = out + (((size_t)b * NOUT) << 10) + l2;
            #pragma unroll
            for (int na = 0; na < 4; na++) {
                const int co = bn + wn * 32 + na * 8 + t * 2;
                op[(size_t)co << 10]       = acc[ma][na][half * 2 + 0];
                op[(size_t)(co + 1) << 10] = acc[ma][na][half * 2 + 1];
            }
        }
    }
}

// ---------------------------------------------------------------------------
extern "C" void kernel_launch(void* const* d_in, const int* in_sizes, int n_in,
                              void* d_out, int out_size) {
    const float* x = (const float*)d_in[0];
    const float* w = (const float*)d_in[1];
    if (n_in >= 2 && in_sizes[0] == 8 * 36 * 64) {   // defensive swap by size
        const float* tp = x; x = w; w = tp;
    }
    float* out = (float*)d_out;

    cudaFuncSetAttribute(gemm_kernel, cudaFuncAttributeMaxDynamicSharedMemorySize, SMEM_TOTAL);

    im2col_kernel<<<dim3(9, IN_CH, BATCH), 256>>>(x);
    beffT_kernel<<<dim3(KF / 256, NOUT), 256>>>(w);
    gemm_kernel<<<dim3(NOUT / 128, MROWS / 128), 256, SMEM_TOTAL>>>(out);
    (void)out_size;
}

// round 5
// speedup vs baseline: 1.2418x; 1.2418x over previous
#include <cuda_runtime.h>
#include <cuda_bf16.h>
#include <cstdint>

// ---------------- problem constants ----------------
#define IN_CH   256
#define BATCH   8
#define KF      2304            // 9*256
#define NOUT    512
#define L2D     1024
#define MROWS   (BATCH * L2D)   // 8192

// GEMM tiling: CTA 128(M) x 256(N), 8 warps (2m x 4n) of 64x64
#define BK   32                 // k per chunk (4 mma k-atoms of 8)
#define NS   3                  // cp.async pipeline stages
#define NCH  (KF / BK)          // 72
#define TSZA (128 * BK * 4)     // 16KB
#define TSZB (256 * BK * 4)     // 32KB
#define STAGE (TSZA + TSZB)     // 48KB
#define SMEM_TOTAL (NS * STAGE) // 144KB

// scratch (__device__ globals: allocation-free rule)
// g_U = im2col buffer [b][f][l] flat == A (8192 x 2304) rows (reference's
// reshape(-1, Q, BLOCK) reinterprets the flat buffer).
__device__ float g_U[(size_t)MROWS * KF];
__device__ float g_BeffT[(size_t)NOUT * KF];   // B^T: [co][k]

// ---------------- helpers ----------------
__device__ __forceinline__ float to_tf32(float v) {
    float r; asm("cvt.rna.tf32.f32 %0, %1;" : "=f"(r) : "f"(v)); return r;
}
__device__ __forceinline__ void cpa16(uint32_t dst, const void* src) {
    asm volatile("cp.async.cg.shared.global [%0], [%1], 16;" :: "r"(dst), "l"(src));
}
#define CP_COMMIT() asm volatile("cp.async.commit_group;" ::: "memory")
#define CP_WAIT1()  asm volatile("cp.async.wait_group 1;" ::: "memory")

// swizzled smem tile: addr(row, k) = row*128 + ((k/4 ^ row%8)*16) + (k%4)*4
__device__ __forceinline__ uint32_t lds32(const char* base, int row, int k) {
    return *(const uint32_t*)(base + row * 128 + (((k >> 2) ^ (row & 7)) << 4) + ((k & 3) << 2));
}
__device__ __forceinline__ void mma8(float* c, const uint32_t* a, const uint32_t* b) {
    asm volatile(
        "mma.sync.aligned.m16n8k8.row.col.f32.tf32.tf32.f32 "
        "{%0,%1,%2,%3}, {%4,%5,%6,%7}, {%8,%9}, {%0,%1,%2,%3};"
        : "+f"(c[0]), "+f"(c[1]), "+f"(c[2]), "+f"(c[3])
        : "r"(a[0]), "r"(a[1]), "r"(a[2]), "r"(a[3]), "r"(b[0]), "r"(b[1]));
}

// ---------------------------------------------------------------------------
// Kernel 1: im2col -> g_U[b][f][l] flat, tf32-rounded. grid (9, 256, 8).
// ---------------------------------------------------------------------------
__global__ void im2col_kernel(const float* __restrict__ x) {
    const int dd = blockIdx.x, ci = blockIdx.y, b = blockIdx.z;
    const int oy = dd / 3 - 1, ox = dd % 3 - 1;      // uniform per block
    const float* xp = x + (((size_t)(b * IN_CH + ci)) << 10);
    float* up = g_U + (((size_t)(b * KF + ci * 9 + dd)) << 10);
    #pragma unroll
    for (int s = 0; s < 4; s++) {
        int l = threadIdx.x + s * 256;
        int h = l >> 5, w = l & 31;
        int y = h + oy, xw = w + ox;
        float v = 0.0f;
        if ((unsigned)y < 32u && (unsigned)xw < 32u) v = xp[(y << 5) + xw];
        up[l] = to_tf32(v);
    }
}

// ---------------------------------------------------------------------------
// Kernel 2: B^T expansion, tf32-rounded. BeffT[co][k] = w[p][q][(j-m)&63]
// ---------------------------------------------------------------------------
__global__ void beffT_kernel(const float* __restrict__ wgt) {
    const int co = blockIdx.y;
    const int k = blockIdx.x * 256 + threadIdx.x;
    const int q = k >> 6, m = k & 63;
    const int p = co >> 6, j = co & 63;
    g_BeffT[(size_t)co * KF + k] = to_tf32(wgt[((p * 36 + q) << 6) + ((j - m) & 63)]);
}

// ---------------------------------------------------------------------------
// Kernel 3: tf32 mma.sync GEMM C[8192,512] = A @ B, fused transpose store.
// CTA 128x256, 8 warps (2m x 4n), warp tile 64x64, 3-stage cp.async.
// ---------------------------------------------------------------------------
__global__ void __launch_bounds__(256, 1) gemm_kernel(float* __restrict__ out) {
    extern __shared__ char sm[];
    const int tid = threadIdx.x;
    const int lane = tid & 31;
    const int wid = tid >> 5;
    const int g = lane >> 2, t = lane & 3;
    const int wm = wid >> 2, wn = wid & 3;       // 2m x 4n
    const int bm = blockIdx.y * 128;
    const int bn = blockIdx.x * 256;

    float acc[4][8][4];
    #pragma unroll
    for (int i = 0; i < 4; i++)
        #pragma unroll
        for (int j = 0; j < 8; j++)
            #pragma unroll
            for (int q = 0; q < 4; q++) acc[i][j][q] = 0.0f;

    auto load_chunk = [&](int c, int s) {
        char* As = sm + s * STAGE;
        char* Bs = As + TSZA;
        const int k0 = c * BK;
        #pragma unroll
        for (int i = 0; i < 4; i++) {            // A: 128 rows x 8 segs
            int id = tid + i * 256;
            int row = id >> 3, cj = id & 7;
            uint32_t swo = (uint32_t)(row * 128 + ((cj ^ (row & 7)) << 4));
            cpa16((uint32_t)__cvta_generic_to_shared(As + swo),
                  &g_U[(size_t)(bm + row) * KF + k0 + cj * 4]);
        }
        #pragma unroll
        for (int i = 0; i < 8; i++) {            // B: 256 rows x 8 segs
            int id = tid + i * 256;
            int row = id >> 3, cj = id & 7;
            uint32_t swo = (uint32_t)(row * 128 + ((cj ^ (row & 7)) << 4));
            cpa16((uint32_t)__cvta_generic_to_shared(Bs + swo),
                  &g_BeffT[(size_t)(bn + row) * KF + k0 + cj * 4]);
        }
    };

    auto compute = [&](int s) {
        const char* As = sm + s * STAGE;
        const char* Bs = As + TSZA;
        #pragma unroll
        for (int ka = 0; ka < 4; ka++) {
            const int k0 = ka * 8;
            uint32_t a[4][4], b[8][2];
            #pragma unroll
            for (int ma = 0; ma < 4; ma++) {
                int r0 = wm * 64 + ma * 16 + g;
                a[ma][0] = lds32(As, r0,     k0 + t);
                a[ma][1] = lds32(As, r0 + 8, k0 + t);
                a[ma][2] = lds32(As, r0,     k0 + t + 4);
                a[ma][3] = lds32(As, r0 + 8, k0 + t + 4);
            }
            #pragma unroll
            for (int na = 0; na < 8; na++) {
                int n0 = wn * 64 + na * 8 + g;
                b[na][0] = lds32(Bs, n0, k0 + t);
                b[na][1] = lds32(Bs, n0, k0 + t + 4);
            }
            #pragma unroll
            for (int ma = 0; ma < 4; ma++)
                #pragma unroll
                for (int na = 0; na < 8; na++)
                    mma8(acc[ma][na], a[ma], b[na]);
        }
    };

    // prologue: prefetch NS-1 chunks
    #pragma unroll
    for (int s = 0; s < NS - 1; s++) { load_chunk(s, s); CP_COMMIT(); }

    for (int c = 0; c < NCH; c++) {
        CP_WAIT1();
        __syncthreads();
        const int cn = c + NS - 1;
        if (cn < NCH) { load_chunk(cn, cn % NS); CP_COMMIT(); }
        compute(c % NS);
    }

    // epilogue: C[r][co] -> out[b][co][l2], r = b*1024 + l2
    #pragma unroll
    for (int ma = 0; ma < 4; ma++) {
        #pragma unroll
        for (int half = 0; half < 2; half++) {
            const int r = bm + wm * 64 + ma * 16 + g + half * 8;
            const int b = r >> 10;
            const int l2 = r & (L2D - 1);
            float* op = out + (((size_t)b * NOUT) << 10) + l2;
            #pragma unroll
            for (int na = 0; na < 8; na++) {
                const int co = bn + wn * 64 + na * 8 + t * 2;
                op[(size_t)co << 10]       = acc[ma][na][half * 2 + 0];
                op[(size_t)(co + 1) << 10] = acc[ma][na][half * 2 + 1];
            }
        }
    }
}

// ---------------------------------------------------------------------------
extern "C" void kernel_launch(void* const* d_in, const int* in_sizes, int n_in,
                              void* d_out, int out_size) {
    const float* x = (const float*)d_in[0];
    const float* w = (const float*)d_in[1];
    if (n_in >= 2 && in_sizes[0] == 8 * 36 * 64) {   // defensive swap by size
        const float* tp = x; x = w; w = tp;
    }
    float* out = (float*)d_out;

    cudaFuncSetAttribute(gemm_kernel, cudaFuncAttributeMaxDynamicSharedMemorySize, SMEM_TOTAL);

    im2col_kernel<<<dim3(9, IN_CH, BATCH), 256>>>(x);
    beffT_kernel<<<dim3(KF / 256, NOUT), 256>>>(w);
    gemm_kernel<<<dim3(NOUT / 256, MROWS / 128), 256, SMEM_TOTAL>>>(out);
    (void)out_size;
}